// round 9
// baseline (speedup 1.0000x reference)
#include <cuda_runtime.h>
#include <cstddef>

// TensorProduct: out[n,p,n3,f] with parity coupling through CG[9,9,25].
// Strategy:
//  - one thread = one (node, channel-pair); packed fp32x2 arithmetic (FFMA2)
//  - parity butterfly: U = s1*s2, V = d1*d2 streams; even = U+V, odd = U-V
//  - CG triangle-rule sparsity (compile-time) fully unrolled; CG values in
//    shared memory, pre-duplicated into both halves of a u64 so a single
//    broadcast LDS.64 feeds fma.rn.f32x2 with no lane-splat MOVs.

using u64 = unsigned long long;

__device__ __forceinline__ u64 f2mul(u64 a, u64 b) {
    u64 d;
    asm("mul.rn.f32x2 %0, %1, %2;" : "=l"(d) : "l"(a), "l"(b));
    return d;
}
__device__ __forceinline__ u64 f2add(u64 a, u64 b) {
    u64 d;
    asm("add.rn.f32x2 %0, %1, %2;" : "=l"(d) : "l"(a), "l"(b));
    return d;
}
__device__ __forceinline__ u64 f2fma(u64 a, u64 b, u64 c) {
    u64 d;
    asm("fma.rn.f32x2 %0, %1, %2, %3;" : "=l"(d) : "l"(a), "l"(b), "l"(c));
    return d;
}

// packed f32x2 constants
#define PK_HALF    0x3F0000003F000000ull  // {0.5f, 0.5f}
#define PK_NEGHALF 0xBF000000BF000000ull  // {-0.5f, -0.5f}
#define PK_NEG1    0xBF800000BF800000ull  // {-1.f, -1.f}

static constexpr int LA = 9;    // flattened (l,m) of x1
static constexpr int LB = 9;    // flattened (l,m) of x2
static constexpr int LC = 25;   // flattened (l,m) of out
static constexpr int FPAIR = 64; // 128 channels as 64 float2 pairs
static constexpr int NODES_PER_BLOCK = 2;
static constexpr int THREADS = NODES_PER_BLOCK * FPAIR; // 128

__global__ __launch_bounds__(THREADS)
void tp_f32x2_kernel(const float* __restrict__ x1,
                     const float* __restrict__ x2,
                     const float* __restrict__ cg,
                     float* __restrict__ out,
                     int n_nodes)
{
    // CG duplicated into both 32-bit halves: LDS.64 -> ready-to-use f32x2 operand
    __shared__ u64 scg[LA * LB * LC]; // 2025 * 8B = 16.2 KB

    {
        const unsigned* cgu = reinterpret_cast<const unsigned*>(cg);
        for (int k = threadIdx.x; k < LA * LB * LC; k += THREADS) {
            u64 v = (u64)cgu[k];
            scg[k] = (v << 32) | v;
        }
    }
    __syncthreads();

    const int node = blockIdx.x * NODES_PER_BLOCK + (threadIdx.x >> 6);
    const int c    = threadIdx.x & (FPAIR - 1);
    if (node >= n_nodes) return;

    const u64* x1u = reinterpret_cast<const u64*>(x1);
    const u64* x2u = reinterpret_cast<const u64*>(x2);
    u64*       ou  = reinterpret_cast<u64*>(out);

    // ---- load + parity butterfly ----
    u64 s1[LA], d1[LA], s2[LB], d2[LB];

    const u64* p0 = x1u + ((size_t)node * 2 * LA) * FPAIR + c;
    #pragma unroll
    for (int l = 0; l < LA; ++l) {
        u64 a0 = p0[l * FPAIR];            // parity even
        u64 a1 = p0[(LA + l) * FPAIR];     // parity odd
        u64 h  = f2mul(a0, PK_HALF);
        s1[l]  = f2fma(a1, PK_HALF,    h); // 0.5*(a0+a1)
        d1[l]  = f2fma(a1, PK_NEGHALF, h); // 0.5*(a0-a1)
    }

    const u64* q0 = x2u + ((size_t)node * 2 * LB) * FPAIR + c;
    #pragma unroll
    for (int m = 0; m < LB; ++m) {
        u64 b0 = q0[m * FPAIR];
        u64 b1 = q0[(LB + m) * FPAIR];
        s2[m]  = f2add(b0, b1);            // (b0+b1)
        d2[m]  = f2fma(b1, PK_NEG1, b0);   // (b0-b1)
    }
    // s1*s2 + d1*d2 = a0*b0 + a1*b1 (even);  s1*s2 - d1*d2 = a0*b1 + a1*b0 (odd)

    // ---- accumulate both streams against sparse CG ----
    u64 accU[LC], accV[LC];
    #pragma unroll
    for (int k = 0; k < LC; ++k) { accU[k] = 0ull; accV[k] = 0ull; }

    #pragma unroll
    for (int i = 0; i < LA; ++i) {
        const int la = (i == 0) ? 0 : ((i < 4) ? 1 : 2);
        #pragma unroll
        for (int j = 0; j < LB; ++j) {
            const int lb = (j == 0) ? 0 : ((j < 4) ? 1 : 2);
            const int lo = (la > lb) ? (la - lb) : (lb - la);
            const int hi = la + lb;
            const u64 U = f2mul(s1[i], s2[j]);
            const u64 V = f2mul(d1[i], d2[j]);
            // triangle rule: nonzero CG only for n3 in [lo^2, (hi+1)^2)
            #pragma unroll
            for (int n3 = lo * lo; n3 < (hi + 1) * (hi + 1); ++n3) {
                const u64 cgv = scg[(i * LB + j) * LC + n3]; // warp-uniform broadcast
                accU[n3] = f2fma(cgv, U, accU[n3]);
                accV[n3] = f2fma(cgv, V, accV[n3]);
            }
        }
    }

    // ---- butterfly back to parities and store ----
    u64* o0 = ou + ((size_t)node * 2 * LC) * FPAIR + c;
    #pragma unroll
    for (int k = 0; k < LC; ++k) {
        o0[k * FPAIR]        = f2add(accU[k], accV[k]);           // even parity
        o0[(LC + k) * FPAIR] = f2fma(accV[k], PK_NEG1, accU[k]);  // odd parity
    }
}

extern "C" void kernel_launch(void* const* d_in, const int* in_sizes, int n_in,
                              void* d_out, int out_size)
{
    const float* x1 = (const float*)d_in[0]; // [N, 2, 9, 128]
    const float* x2 = (const float*)d_in[1]; // [N, 2, 9, 128]
    const float* cg = (const float*)d_in[2]; // [9, 9, 25]
    float* out = (float*)d_out;              // [N, 2, 25, 128]

    const int n_nodes = in_sizes[0] / (2 * LA * 128);
    const int grid = (n_nodes + NODES_PER_BLOCK - 1) / NODES_PER_BLOCK;

    tp_f32x2_kernel<<<grid, THREADS>>>(x1, x2, cg, out, n_nodes);
}